// round 14
// baseline (speedup 1.0000x reference)
#include <cuda_runtime.h>

#define Bn 16
#define Nn 1024
#define Dn 8
#define Cn 128
#define Hn 256
#define NCOND 3
#define MAXIT 4
#define NROWS (Bn * Nn)
#define GRID 128
#define TPB 512
#define FLT_BIG 3.402823466e38f

// ---------------- device scratch (no allocations allowed) ----------------
__device__ __align__(16) float g_x0[NROWS * Dn];   // 512 KB
__device__ float g_cc[Bn * Hn];
__device__ int g_cnt[MAXIT + 1][Bn];               // per-(pass, batch) masked count
__device__ int g_lists[2][Bn][Nn];                 // ping-pong per-batch masked row lists
__device__ float g_partial[GRID];
__device__ unsigned int g_barc[8];                 // monotonic barrier counters (never reset)

// Software grid barrier. GRID=128 blocks <= 148 SMs at occupancy 1 -> all
// co-resident; monotonic counters need no reset and are replay-deterministic.
__device__ __forceinline__ void gbar(int i) {
    __threadfence();
    __syncthreads();
    if (threadIdx.x == 0) {
        unsigned int old = atomicAdd(&g_barc[i], 1u);
        unsigned int target = (old & ~(unsigned int)(GRID - 1)) + (unsigned int)GRID;
        while (atomicAdd(&g_barc[i], 0u) < target) { __nanosleep(32); }
        __threadfence();
    }
    __syncthreads();
}

__device__ __forceinline__ float tanh_fast(float x) {
    float y;
    asm("tanh.approx.f32 %0, %1;" : "=f"(y) : "f"(x));
    return y;
}

// Packed-f32x2 squared distance. The smem tile holds NEGATED data, so
// t = x + (-d) == x - d exactly; acc pairs (even dims, odd dims), final lo+hi.
// All distances (incl. d_self) use this same sequence -> self-consistent.
__device__ __forceinline__ float pdist(
    unsigned long long x01, unsigned long long x23,
    unsigned long long x45, unsigned long long x67,
    unsigned long long d01, unsigned long long d23,
    unsigned long long d45, unsigned long long d67) {
    unsigned long long t, acc;
    asm("add.rn.f32x2 %0, %1, %2;" : "=l"(t) : "l"(x01), "l"(d01));
    asm("mul.rn.f32x2 %0, %1, %1;" : "=l"(acc) : "l"(t));
    asm("add.rn.f32x2 %0, %1, %2;" : "=l"(t) : "l"(x23), "l"(d23));
    asm("fma.rn.f32x2 %0, %1, %1, %2;" : "=l"(acc) : "l"(t), "l"(acc));
    asm("add.rn.f32x2 %0, %1, %2;" : "=l"(t) : "l"(x45), "l"(d45));
    asm("fma.rn.f32x2 %0, %1, %1, %2;" : "=l"(acc) : "l"(t), "l"(acc));
    asm("add.rn.f32x2 %0, %1, %2;" : "=l"(t) : "l"(x67), "l"(d67));
    asm("fma.rn.f32x2 %0, %1, %1, %2;" : "=l"(acc) : "l"(t), "l"(acc));
    unsigned int lo, hi;
    asm("mov.b64 {%0, %1}, %2;" : "=r"(lo), "=r"(hi) : "l"(acc));
    return __uint_as_float(lo) + __uint_as_float(hi);
}

// smem float4 index for data row m (pad 1 float4 per 32 rows). Lane l owns
// m = 32l + i -> idx = 65l + 2i; per 8-lane LDS.128 phase, bank-quads
// (l + 2i) mod 8 are all distinct -> conflict-free.
#define SIDX(m) (2 * (m) + ((m) >> 5))

__global__ void __launch_bounds__(TPB, 1) k_fused(
    const float* __restrict__ data, const float* __restrict__ c,
    const float* __restrict__ tv,   const float* __restrict__ x0_noise,
    const float* __restrict__ noise_bank,
    const float* __restrict__ W1,   const float* __restrict__ Wc,
    const float* __restrict__ Wt,   const float* __restrict__ b1,
    const float* __restrict__ W2,   float* __restrict__ out) {

    // 33.3 KB negated tile (phases 1-2), aliased by weights in phase 3
    __shared__ __align__(16) float smem_raw[(Nn * 2 + 64) * 4];
    __shared__ float sred[TPB];
    float4* sdata = (float4*)smem_raw;
    const ulonglong2* sd64 = (const ulonglong2*)smem_raw;
    float*  sW1   = smem_raw;
    float*  sW2   = smem_raw + Dn * Hn;
    float*  sbase = smem_raw + 2 * Dn * Hn;

    const int t   = threadIdx.x;
    const int bid = blockIdx.x;
    const int gid = bid * TPB + t;
    const int b    = bid >> 3;           // batch owned by this block
    const int tile = bid & 7;
    const int lane = t & 31;
    const int wid  = t >> 5;             // 0..15

    // ---------------- phase 0: zero counters, init x0, cc = c @ Wc --------
    if (gid < (MAXIT + 1) * Bn) ((int*)g_cnt)[gid] = 0;
    for (int i = gid; i < NROWS * Dn; i += GRID * TPB) {
        int d = i & (Dn - 1);
        g_x0[i] = (d < NCOND) ? data[i] : x0_noise[i];
    }
    {   // all blocks compute cc redundantly (identical values) -> no skew
        int e = gid & (Bn * Hn - 1);
        int bb = e >> 8, h = e & (Hn - 1);
        float acc = 0.f;
        #pragma unroll 8
        for (int j = 0; j < Cn; j++)
            acc = fmaf(c[bb * Cn + j], Wc[j * Hn + h], acc);
        g_cc[e] = acc;
    }

    // ---------------- load NEGATED data[b] tile into smem (padded) --------
    {
        const float4* dptr = (const float4*)(data + (size_t)b * Nn * Dn);
        for (int i = t; i < Nn * 2; i += TPB) {
            int m = i >> 1;
            float4 v = dptr[i];
            v.x = -v.x; v.y = -v.y; v.z = -v.z; v.w = -v.w;
            sdata[SIDX(m) + (i & 1)] = v;
        }
    }
    gbar(0);   // also orders the smem tile via its __syncthreads

    const int sbase32 = 65 * lane;       // SIDX(lane*32)

    // ---------------- phase 1: mismatch predicate, 8 rows/warp, early exit
    // mismatch(n) <=> exists m: d_m < d_self || (d_m == d_self && m < n)
    // (exactly first-index argmin != n; m==n gives d==d_self, excluded)
    // Exactly ONE 8-row group per warp: rows tile*128 + wid*8 + (0..7).
    {
        unsigned long long x01[8], x23[8], x45[8], x67[8];
        float dself[8];
        const int rowbase = tile * 128 + wid * 8;
        unsigned int found = 0u;
        #pragma unroll
        for (int j = 0; j < 8; j++) {
            const float4* xr =
                (const float4*)(g_x0 + ((size_t)b * Nn + rowbase + j) * Dn);
            float4 v0 = xr[0], v1 = xr[1];          // broadcast
            ulonglong2 p0 = *(ulonglong2*)&v0;
            ulonglong2 p1 = *(ulonglong2*)&v1;
            x01[j] = p0.x; x23[j] = p0.y; x45[j] = p1.x; x67[j] = p1.y;
            ulonglong2 sa = sd64[SIDX(rowbase + j)];
            ulonglong2 sb = sd64[SIDX(rowbase + j) + 1];
            dself[j] = pdist(x01[j], x23[j], x45[j], x67[j], sa.x, sa.y, sb.x, sb.y);
        }
        unsigned int warpFound = 0u;
        #pragma unroll 1
        for (int i8 = 0; i8 < 4; i8++) {
            #pragma unroll
            for (int k = 0; k < 8; k++) {
                int i = i8 * 8 + k;
                ulonglong2 da = sd64[sbase32 + 2 * i];
                ulonglong2 db = sd64[sbase32 + 2 * i + 1];
                int m = lane * 32 + i;
                #pragma unroll
                for (int j = 0; j < 8; j++) {
                    float d = pdist(x01[j], x23[j], x45[j], x67[j],
                                    da.x, da.y, db.x, db.y);
                    unsigned int hit = (unsigned int)((d < dself[j]) |
                                       ((d == dself[j]) & (m < rowbase + j)));
                    found |= hit << j;
                }
            }
            warpFound = __reduce_or_sync(0xffffffffu, found);
            if (warpFound == 0xFFu) break;
        }
        if (lane == 0) {
            int nm = 0, mr[8];
            #pragma unroll
            for (int j = 0; j < 8; j++)
                if ((warpFound >> j) & 1u) mr[nm++] = rowbase + j;
            if (nm) {
                int s = atomicAdd(&g_cnt[0][b], nm);
                for (int k = 0; k < nm; k++) g_lists[0][b][s + k] = mr[k];
            }
        }
    }
    gbar(1);

    // ---------------- phase 2: iterative renoise (smem tile reuse) --------
    // Unmasked rows invariant => only listed rows renoised + rechecked.
    const int wb = (bid & 7) * 16 + wid;   // warp index within batch: 0..127
    for (int it = 0; it < MAXIT; it++) {
        int total = 0;
        #pragma unroll
        for (int i = 0; i < Bn; i++) total += g_cnt[it][i];
        if (total >= 10) {               // while-loop condition (global mask sum)
            const int cnt = g_cnt[it][b];
            const int* src = g_lists[it & 1][b];
            int*       dst = g_lists[(it + 1) & 1][b];
            const int ng = (cnt + 7) >> 3;          // 8 rows per warp-group
            for (int g = wb; g < ng; g += 128) {
                unsigned long long x01[8], x23[8], x45[8], x67[8];
                float dself[8];
                int rn[8];
                unsigned int valmask = 0u, found = 0u;
                #pragma unroll
                for (int j = 0; j < 8; j++) {
                    int li = g * 8 + j;
                    bool val = li < cnt;
                    valmask |= ((unsigned int)val) << j;
                    found |= ((unsigned int)!val) << j;  // invalid: pre-decided
                    rn[j] = val ? src[li] : 0;
                    int rf = b * Nn + rn[j];
                    // x row = [data dims 0-2, noise_bank[it] dims 3-7]
                    float4 dA = ((const float4*)data)[(size_t)rf * 2];
                    const float4* np =
                        (const float4*)(noise_bank + ((size_t)it * NROWS + rf) * Dn);
                    float4 nA = np[0], nB = np[1];
                    float4 vA = make_float4(dA.x, dA.y, dA.z, nA.w);
                    ulonglong2 p0 = *(ulonglong2*)&vA;
                    ulonglong2 p1 = *(ulonglong2*)&nB;
                    x01[j] = p0.x; x23[j] = p0.y; x45[j] = p1.x; x67[j] = p1.y;
                    if (lane == 0 && val) {          // persist renoise for phase 3
                        g_x0[(size_t)rf * Dn + 3] = nA.w;
                        *((float4*)(g_x0 + (size_t)rf * Dn + 4)) = nB;
                    }
                    ulonglong2 sa = sd64[SIDX(rn[j])];
                    ulonglong2 sb = sd64[SIDX(rn[j]) + 1];
                    dself[j] = pdist(x01[j], x23[j], x45[j], x67[j],
                                     sa.x, sa.y, sb.x, sb.y);
                }
                unsigned int warpFound = 0u;
                #pragma unroll 1
                for (int i8 = 0; i8 < 4; i8++) {
                    #pragma unroll
                    for (int k = 0; k < 8; k++) {
                        int i = i8 * 8 + k;
                        ulonglong2 da = sd64[sbase32 + 2 * i];
                        ulonglong2 db = sd64[sbase32 + 2 * i + 1];
                        int m = lane * 32 + i;
                        #pragma unroll
                        for (int j = 0; j < 8; j++) {
                            float d = pdist(x01[j], x23[j], x45[j], x67[j],
                                            da.x, da.y, db.x, db.y);
                            unsigned int hit = (unsigned int)((d < dself[j]) |
                                               ((d == dself[j]) & (m < rn[j])));
                            found |= hit << j;
                        }
                    }
                    warpFound = __reduce_or_sync(0xffffffffu, found);
                    if (warpFound == 0xFFu) break;
                }
                if (lane == 0) {
                    unsigned int mis = warpFound & valmask;
                    int nm = 0, mr[8];
                    #pragma unroll
                    for (int j = 0; j < 8; j++)
                        if ((mis >> j) & 1u) mr[nm++] = rn[j];
                    if (nm) {
                        int s = atomicAdd(&g_cnt[it + 1][b], nm);
                        for (int k = 0; k < nm; k++) dst[s + k] = mr[k];
                    }
                }
            }
        }
        gbar(2 + it);
    }

    // ---------------- phase 3: fused model + masked loss ------------------
    {
        for (int i = t; i < Dn * Hn; i += TPB) sW1[i] = W1[i];
        for (int i = t; i < Hn * Dn; i += TPB) sW2[i] = W2[i];
        const float tb = tv[b];
        if (t < Hn)
            sbase[t] = g_cc[b * Hn + t] + tb * Wt[t] + b1[t];
        __syncthreads();

        const int q   = t & 3;            // h-quarter: [q*64, q*64+64)
        const int r   = t >> 2;           // 0..127
        const int row = tile * 128 + r;
        const int base = (b * Nn + row) * Dn;

        float xt[Dn], ut[Dn], vt[Dn];
        #pragma unroll
        for (int d = 0; d < Dn; d++) {
            float dv = data[base + d];
            float xv = g_x0[base + d];
            ut[d] = dv - xv;
            xt[d] = (d < NCOND) ? dv : ((1.0f - tb) * xv + tb * dv);
            vt[d] = 0.f;
        }
        const int h0 = q * (Hn / 4);
        for (int h = h0; h < h0 + Hn / 4; h++) {
            float pre = sbase[h];
            #pragma unroll
            for (int d = 0; d < Dn; d++) pre = fmaf(xt[d], sW1[d * Hn + h], pre);
            float hh = tanh_fast(pre);
            #pragma unroll
            for (int d = 0; d < Dn; d++) vt[d] = fmaf(hh, sW2[h * Dn + d], vt[d]);
        }
        // merge h-quarters (lanes 4r..4r+3)
        #pragma unroll
        for (int off = 2; off >= 1; off >>= 1) {
            #pragma unroll
            for (int d = 0; d < Dn; d++)
                vt[d] += __shfl_down_sync(0xffffffffu, vt[d], off, 4);
        }
        float part = 0.f;
        if (q == 0) {
            #pragma unroll
            for (int d = NCOND; d < Dn; d++) {
                float e = vt[d] - ut[d];
                part = fmaf(e, e, part);
            }
        }
        sred[t] = part;
        __syncthreads();
        // deterministic tree reduction
        for (int s = TPB / 2; s > 0; s >>= 1) {
            if (t < s) sred[t] += sred[t + s];
            __syncthreads();
        }
        if (t == 0) g_partial[bid] = sred[0];
    }
    gbar(6);

    // ---------------- phase 4: per-batch deterministic sum ----------------
    if (bid == 0 && t < Bn) {
        float s = 0.f;
        #pragma unroll
        for (int i = 0; i < 8; i++) s += g_partial[t * 8 + i];
        out[t] = s / (float)(Nn * (Dn - NCOND));
    }
}

// ---------------- launch: ONE graph node ----------------------------------
extern "C" void kernel_launch(void* const* d_in, const int* in_sizes, int n_in,
                              void* d_out, int out_size) {
    const float* data = (const float*)d_in[0];
    const float* c    = (const float*)d_in[1];
    const float* t    = (const float*)d_in[2];
    const float* x0n  = (const float*)d_in[3];
    const float* nb   = (const float*)d_in[4];
    const float* W1   = (const float*)d_in[5];
    const float* Wc   = (const float*)d_in[6];
    const float* Wt   = (const float*)d_in[7];
    const float* b1   = (const float*)d_in[8];
    const float* W2   = (const float*)d_in[9];
    float* out = (float*)d_out;

    k_fused<<<GRID, TPB>>>(data, c, t, x0n, nb, W1, Wc, Wt, b1, W2, out);
}

// round 15
// speedup vs baseline: 1.0488x; 1.0488x over previous
#include <cuda_runtime.h>

#define Bn 16
#define Nn 1024
#define Dn 8
#define Cn 128
#define Hn 256
#define NCOND 3
#define MAXIT 4
#define NROWS (Bn * Nn)
#define GRID 128
#define TPB 512
#define FLT_BIG 3.402823466e38f

// ---------------- device scratch (no allocations allowed) ----------------
__device__ __align__(16) float g_x0[NROWS * Dn];   // 512 KB
__device__ float g_cc[Bn * Hn];
__device__ int g_cnt[MAXIT + 1][Bn];               // per-(pass, batch) masked count
__device__ int g_lists[2][Bn][Nn];                 // ping-pong per-batch masked row lists
__device__ float g_partial[GRID];
__device__ unsigned int g_barc[8];                 // monotonic barrier counters (never reset)

// Software grid barrier. GRID=128 blocks <= 148 SMs at occupancy 1 -> all
// co-resident; monotonic counters need no reset and are replay-deterministic.
__device__ __forceinline__ void gbar(int i) {
    __threadfence();
    __syncthreads();
    if (threadIdx.x == 0) {
        unsigned int old = atomicAdd(&g_barc[i], 1u);
        unsigned int target = (old & ~(unsigned int)(GRID - 1)) + (unsigned int)GRID;
        while (atomicAdd(&g_barc[i], 0u) < target) { __nanosleep(32); }
        __threadfence();
    }
    __syncthreads();
}

__device__ __forceinline__ float tanh_fast(float x) {
    float y;
    asm("tanh.approx.f32 %0, %1;" : "=f"(y) : "f"(x));
    return y;
}

// Packed-f32x2 squared distance, SPLIT ACCUMULATORS (short chain).
// The smem tile holds NEGATED data, so t = x + (-d) == x - d exactly.
// Two independent chains (dims 0,1,4,5 and 2,3,6,7) merged at the end:
// depth ~28 cyc vs ~53 for the single-chain version. Used identically for
// ALL distances (incl. d_self) -> comparisons stay self-consistent.
__device__ __forceinline__ float pdist(
    unsigned long long x01, unsigned long long x23,
    unsigned long long x45, unsigned long long x67,
    unsigned long long d01, unsigned long long d23,
    unsigned long long d45, unsigned long long d67) {
    unsigned long long t0, t1, t2, t3, a0, a1;
    asm("add.rn.f32x2 %0, %1, %2;" : "=l"(t0) : "l"(x01), "l"(d01));
    asm("add.rn.f32x2 %0, %1, %2;" : "=l"(t1) : "l"(x23), "l"(d23));
    asm("add.rn.f32x2 %0, %1, %2;" : "=l"(t2) : "l"(x45), "l"(d45));
    asm("add.rn.f32x2 %0, %1, %2;" : "=l"(t3) : "l"(x67), "l"(d67));
    asm("mul.rn.f32x2 %0, %1, %1;" : "=l"(a0) : "l"(t0));
    asm("mul.rn.f32x2 %0, %1, %1;" : "=l"(a1) : "l"(t1));
    asm("fma.rn.f32x2 %0, %1, %1, %2;" : "=l"(a0) : "l"(t2), "l"(a0));
    asm("fma.rn.f32x2 %0, %1, %1, %2;" : "=l"(a1) : "l"(t3), "l"(a1));
    asm("add.rn.f32x2 %0, %1, %2;" : "=l"(a0) : "l"(a0), "l"(a1));
    unsigned int lo, hi;
    asm("mov.b64 {%0, %1}, %2;" : "=r"(lo), "=r"(hi) : "l"(a0));
    return __uint_as_float(lo) + __uint_as_float(hi);
}

// smem float4 index for data row m (pad 1 float4 per 32 rows). Lane l owns
// m = 32l + i -> idx = 65l + 2i; per 8-lane LDS.128 phase, bank-quads
// (l + 2i) mod 8 are all distinct -> conflict-free.
#define SIDX(m) (2 * (m) + ((m) >> 5))

__global__ void __launch_bounds__(TPB, 1) k_fused(
    const float* __restrict__ data, const float* __restrict__ c,
    const float* __restrict__ tv,   const float* __restrict__ x0_noise,
    const float* __restrict__ noise_bank,
    const float* __restrict__ W1,   const float* __restrict__ Wc,
    const float* __restrict__ Wt,   const float* __restrict__ b1,
    const float* __restrict__ W2,   float* __restrict__ out) {

    // 33.3 KB negated tile (phases 1-2), aliased by weights in phase 3
    __shared__ __align__(16) float smem_raw[(Nn * 2 + 64) * 4];
    __shared__ float sred[TPB];
    float4* sdata = (float4*)smem_raw;
    const ulonglong2* sd64 = (const ulonglong2*)smem_raw;
    float*  sW1   = smem_raw;
    float*  sW2   = smem_raw + Dn * Hn;
    float*  sbase = smem_raw + 2 * Dn * Hn;

    const int t   = threadIdx.x;
    const int bid = blockIdx.x;
    const int gid = bid * TPB + t;
    const int b    = bid >> 3;           // batch owned by this block
    const int tile = bid & 7;
    const int lane = t & 31;
    const int wid  = t >> 5;             // 0..15

    // ---------------- phase 0: zero counters, init x0, cc = c @ Wc --------
    if (gid < (MAXIT + 1) * Bn) ((int*)g_cnt)[gid] = 0;
    for (int i = gid; i < NROWS * Dn; i += GRID * TPB) {
        int d = i & (Dn - 1);
        g_x0[i] = (d < NCOND) ? data[i] : x0_noise[i];
    }
    if (gid < Bn * Hn) {
        int bb = gid >> 8, h = gid & (Hn - 1);
        float acc = 0.f;
        #pragma unroll 8
        for (int j = 0; j < Cn; j++)
            acc = fmaf(c[bb * Cn + j], Wc[j * Hn + h], acc);
        g_cc[gid] = acc;
    }

    // ---------------- load NEGATED data[b] tile into smem (padded) --------
    {
        const float4* dptr = (const float4*)(data + (size_t)b * Nn * Dn);
        for (int i = t; i < Nn * 2; i += TPB) {
            int m = i >> 1;
            float4 v = dptr[i];
            v.x = -v.x; v.y = -v.y; v.z = -v.z; v.w = -v.w;
            sdata[SIDX(m) + (i & 1)] = v;
        }
    }
    gbar(0);   // also orders the smem tile via its __syncthreads

    const int sbase32 = 65 * lane;       // SIDX(lane*32)

    // ---------------- phase 1: mismatch predicate, 4 rows/warp, early exit
    // mismatch(n) <=> exists m: d_m < d_self || (d_m == d_self && m < n)
    // (exactly first-index argmin != n; m==n gives d==d_self, excluded)
    #pragma unroll 1
    for (int pass = 0; pass < 2; pass++) {
        unsigned long long x01[4], x23[4], x45[4], x67[4];
        float dself[4];
        int rown[4];
        bool found[4];
        #pragma unroll
        for (int j = 0; j < 4; j++) {
            rown[j] = tile * 128 + pass * 64 + wid * 4 + j;
            const float4* xr = (const float4*)(g_x0 + ((size_t)b * Nn + rown[j]) * Dn);
            float4 v0 = xr[0], v1 = xr[1];          // broadcast
            ulonglong2 p0 = *(ulonglong2*)&v0;
            ulonglong2 p1 = *(ulonglong2*)&v1;
            x01[j] = p0.x; x23[j] = p0.y; x45[j] = p1.x; x67[j] = p1.y;
            ulonglong2 sa = sd64[SIDX(rown[j])];
            ulonglong2 sb = sd64[SIDX(rown[j]) + 1];
            dself[j] = pdist(x01[j], x23[j], x45[j], x67[j], sa.x, sa.y, sb.x, sb.y);
            found[j] = false;
        }
        #pragma unroll 1
        for (int i8 = 0; i8 < 4; i8++) {
            #pragma unroll
            for (int k = 0; k < 8; k++) {
                int i = i8 * 8 + k;
                ulonglong2 da = sd64[sbase32 + 2 * i];
                ulonglong2 db = sd64[sbase32 + 2 * i + 1];
                int m = lane * 32 + i;
                #pragma unroll
                for (int j = 0; j < 4; j++) {
                    float d = pdist(x01[j], x23[j], x45[j], x67[j],
                                    da.x, da.y, db.x, db.y);
                    found[j] |= (d < dself[j]) | ((d == dself[j]) & (m < rown[j]));
                }
            }
            if (__any_sync(0xffffffffu, found[0]) &
                __any_sync(0xffffffffu, found[1]) &
                __any_sync(0xffffffffu, found[2]) &
                __any_sync(0xffffffffu, found[3])) break;
        }
        #pragma unroll
        for (int j = 0; j < 4; j++) {
            bool mis = __any_sync(0xffffffffu, found[j]);
            if (lane == 0 && mis) {
                int s = atomicAdd(&g_cnt[0][b], 1);
                g_lists[0][b][s] = rown[j];
            }
        }
    }
    gbar(1);

    // ---------------- phase 2: iterative renoise (smem tile reuse) --------
    // Unmasked rows invariant => only listed rows renoised + rechecked.
    const int wb = (bid & 7) * 16 + wid;   // warp index within batch: 0..127
    for (int it = 0; it < MAXIT; it++) {
        int total = 0;
        #pragma unroll
        for (int i = 0; i < Bn; i++) total += g_cnt[it][i];
        if (total >= 10) {               // while-loop condition (global mask sum)
            const int cnt = g_cnt[it][b];
            const int* src = g_lists[it & 1][b];
            int*       dst = g_lists[(it + 1) & 1][b];
            const int ng = (cnt + 3) >> 2;          // 4 rows per warp-group
            for (int g = wb; g < ng; g += 128) {
                unsigned long long x01[4], x23[4], x45[4], x67[4];
                float dself[4];
                int rn[4];
                bool val[4], found[4];
                #pragma unroll
                for (int j = 0; j < 4; j++) {
                    int li = g * 4 + j;
                    val[j] = li < cnt;
                    rn[j] = val[j] ? src[li] : 0;
                    int rf = b * Nn + rn[j];
                    // x row = [data dims 0-2, noise_bank[it] dims 3-7]
                    float4 dA = ((const float4*)data)[(size_t)rf * 2];
                    const float4* np =
                        (const float4*)(noise_bank + ((size_t)it * NROWS + rf) * Dn);
                    float4 nA = np[0], nB = np[1];
                    float4 vA = make_float4(dA.x, dA.y, dA.z, nA.w);
                    ulonglong2 p0 = *(ulonglong2*)&vA;
                    ulonglong2 p1 = *(ulonglong2*)&nB;
                    x01[j] = p0.x; x23[j] = p0.y; x45[j] = p1.x; x67[j] = p1.y;
                    if (lane == 0 && val[j]) {       // persist renoise for phase 3
                        g_x0[(size_t)rf * Dn + 3] = nA.w;
                        *((float4*)(g_x0 + (size_t)rf * Dn + 4)) = nB;
                    }
                    ulonglong2 sa = sd64[SIDX(rn[j])];
                    ulonglong2 sb = sd64[SIDX(rn[j]) + 1];
                    dself[j] = pdist(x01[j], x23[j], x45[j], x67[j],
                                     sa.x, sa.y, sb.x, sb.y);
                    found[j] = !val[j];              // invalid rows don't block exit
                }
                #pragma unroll 1
                for (int i8 = 0; i8 < 4; i8++) {
                    #pragma unroll
                    for (int k = 0; k < 8; k++) {
                        int i = i8 * 8 + k;
                        ulonglong2 da = sd64[sbase32 + 2 * i];
                        ulonglong2 db = sd64[sbase32 + 2 * i + 1];
                        int m = lane * 32 + i;
                        #pragma unroll
                        for (int j = 0; j < 4; j++) {
                            float d = pdist(x01[j], x23[j], x45[j], x67[j],
                                            da.x, da.y, db.x, db.y);
                            found[j] |= (d < dself[j]) | ((d == dself[j]) & (m < rn[j]));
                        }
                    }
                    if (__any_sync(0xffffffffu, found[0]) &
                        __any_sync(0xffffffffu, found[1]) &
                        __any_sync(0xffffffffu, found[2]) &
                        __any_sync(0xffffffffu, found[3])) break;
                }
                #pragma unroll
                for (int j = 0; j < 4; j++) {
                    bool mis = __any_sync(0xffffffffu, found[j]);
                    if (lane == 0 && val[j] && mis) {
                        int s = atomicAdd(&g_cnt[it + 1][b], 1);
                        dst[s] = rn[j];
                    }
                }
            }
        }
        gbar(2 + it);
    }

    // ---------------- phase 3: fused model + masked loss ------------------
    {
        for (int i = t; i < Dn * Hn; i += TPB) sW1[i] = W1[i];
        for (int i = t; i < Hn * Dn; i += TPB) sW2[i] = W2[i];
        const float tb = tv[b];
        if (t < Hn)
            sbase[t] = g_cc[b * Hn + t] + tb * Wt[t] + b1[t];
        __syncthreads();

        const int q   = t & 3;            // h-quarter: [q*64, q*64+64)
        const int r   = t >> 2;           // 0..127
        const int row = tile * 128 + r;
        const int base = (b * Nn + row) * Dn;

        float xt[Dn], ut[Dn], vt[Dn];
        #pragma unroll
        for (int d = 0; d < Dn; d++) {
            float dv = data[base + d];
            float xv = g_x0[base + d];
            ut[d] = dv - xv;
            xt[d] = (d < NCOND) ? dv : ((1.0f - tb) * xv + tb * dv);
            vt[d] = 0.f;
        }
        const int h0 = q * (Hn / 4);
        for (int h = h0; h < h0 + Hn / 4; h++) {
            float pre = sbase[h];
            #pragma unroll
            for (int d = 0; d < Dn; d++) pre = fmaf(xt[d], sW1[d * Hn + h], pre);
            float hh = tanh_fast(pre);
            #pragma unroll
            for (int d = 0; d < Dn; d++) vt[d] = fmaf(hh, sW2[h * Dn + d], vt[d]);
        }
        // merge h-quarters (lanes 4r..4r+3)
        #pragma unroll
        for (int off = 2; off >= 1; off >>= 1) {
            #pragma unroll
            for (int d = 0; d < Dn; d++)
                vt[d] += __shfl_down_sync(0xffffffffu, vt[d], off, 4);
        }
        float part = 0.f;
        if (q == 0) {
            #pragma unroll
            for (int d = NCOND; d < Dn; d++) {
                float e = vt[d] - ut[d];
                part = fmaf(e, e, part);
            }
        }
        sred[t] = part;
        __syncthreads();
        // deterministic tree reduction
        for (int s = TPB / 2; s > 0; s >>= 1) {
            if (t < s) sred[t] += sred[t + s];
            __syncthreads();
        }
        if (t == 0) g_partial[bid] = sred[0];
    }
    gbar(6);

    // ---------------- phase 4: per-batch deterministic sum ----------------
    if (bid == 0 && t < Bn) {
        float s = 0.f;
        #pragma unroll
        for (int i = 0; i < 8; i++) s += g_partial[t * 8 + i];
        out[t] = s / (float)(Nn * (Dn - NCOND));
    }
}

// ---------------- launch: ONE graph node ----------------------------------
extern "C" void kernel_launch(void* const* d_in, const int* in_sizes, int n_in,
                              void* d_out, int out_size) {
    const float* data = (const float*)d_in[0];
    const float* c    = (const float*)d_in[1];
    const float* t    = (const float*)d_in[2];
    const float* x0n  = (const float*)d_in[3];
    const float* nb   = (const float*)d_in[4];
    const float* W1   = (const float*)d_in[5];
    const float* Wc   = (const float*)d_in[6];
    const float* Wt   = (const float*)d_in[7];
    const float* b1   = (const float*)d_in[8];
    const float* W2   = (const float*)d_in[9];
    float* out = (float*)d_out;

    k_fused<<<GRID, TPB>>>(data, c, t, x0n, nb, W1, Wc, Wt, b1, W2, out);
}

// round 16
// speedup vs baseline: 1.1970x; 1.1413x over previous
#include <cuda_runtime.h>

#define Bn 16
#define Nn 1024
#define Dn 8
#define Cn 128
#define Hn 256
#define NCOND 3
#define MAXIT 4
#define NROWS (Bn * Nn)
#define GRID 128
#define TPB 512

// ---------------- device scratch (no allocations allowed) ----------------
__device__ __align__(16) float g_x0[NROWS * Dn];   // 512 KB
__device__ float g_cc[Bn * Hn];
__device__ int g_cnt[MAXIT + 1][Bn];               // per-(pass, batch) masked count
__device__ int g_lists[2][Bn][Nn];                 // ping-pong per-batch masked row lists
__device__ float g_partial[GRID];
__device__ unsigned int g_barc[8];                 // monotonic barrier counters (never reset)

// Software grid barrier. GRID=128 blocks <= 148 SMs at occupancy 1 -> all
// co-resident; monotonic counters need no reset and are replay-deterministic.
__device__ __forceinline__ void gbar(int i) {
    __threadfence();
    __syncthreads();
    if (threadIdx.x == 0) {
        unsigned int old = atomicAdd(&g_barc[i], 1u);
        unsigned int target = (old & ~(unsigned int)(GRID - 1)) + (unsigned int)GRID;
        while (atomicAdd(&g_barc[i], 0u) < target) { __nanosleep(32); }
        __threadfence();
    }
    __syncthreads();
}

__device__ __forceinline__ float tanh_fast(float x) {
    float y;
    asm("tanh.approx.f32 %0, %1;" : "=f"(y) : "f"(x));
    return y;
}

// smem float4 index for data row m (pad 1 float4 per 32 rows). Lane l owns
// m = 32l + i -> idx = 65l + 2i; per 8-lane LDS.128 phase, bank-quads
// (l + 2i) mod 8 are all distinct -> conflict-free.
#define SIDX(m) (2 * (m) + ((m) >> 5))
// half-norm array index (pad 1 float per 32): lane l, iter i -> 33l + i,
// bank (l + i) mod 32 -> conflict-free.
#define HIDX(m) ((m) + ((m) >> 5))

// score = hm + sum_d nx[d]*m[d], two independent FMA chains (even/odd dims).
// d_m = |x|^2 + 2*score_m -> same ordering as distance. Used IDENTICALLY for
// scan scores and score_self -> m==n compares exactly equal (self-excluded).
__device__ __forceinline__ float score8(const float* nx, float4 da, float4 db,
                                        float hm) {
    float a0 = nx[0] * da.x;
    float a1 = nx[1] * da.y;
    a0 = fmaf(nx[2], da.z, a0);
    a1 = fmaf(nx[3], da.w, a1);
    a0 = fmaf(nx[4], db.x, a0);
    a1 = fmaf(nx[5], db.y, a1);
    a0 = fmaf(nx[6], db.z, a0);
    a1 = fmaf(nx[7], db.w, a1);
    return hm + a0 + a1;
}

__global__ void __launch_bounds__(TPB, 1) k_fused(
    const float* __restrict__ data, const float* __restrict__ c,
    const float* __restrict__ tv,   const float* __restrict__ x0_noise,
    const float* __restrict__ noise_bank,
    const float* __restrict__ W1,   const float* __restrict__ Wc,
    const float* __restrict__ Wt,   const float* __restrict__ b1,
    const float* __restrict__ W2,   float* __restrict__ out) {

    // raw data tile (33.3 KB) + half-norms (4.2 KB) + reduction buffer
    __shared__ __align__(16) float smem_raw[(Nn * 2 + 64) * 4];
    __shared__ float shm[Nn + 32];
    __shared__ float sred[TPB];
    float4* sdata = (float4*)smem_raw;
    float*  sW1   = smem_raw;            // phase 3 aliases of the tile region
    float*  sW2   = smem_raw + Dn * Hn;
    float*  sbase = smem_raw + 2 * Dn * Hn;

    const int t   = threadIdx.x;
    const int bid = blockIdx.x;
    const int gid = bid * TPB + t;
    const int b    = bid >> 3;           // batch owned by this block
    const int tile = bid & 7;
    const int lane = t & 31;
    const int wid  = t >> 5;             // 0..15

    // ---------------- phase 0: counters, x0 init, cc = c @ Wc -------------
    if (gid < (MAXIT + 1) * Bn) ((int*)g_cnt)[gid] = 0;
    for (int i = gid; i < NROWS * Dn; i += GRID * TPB) {
        int d = i & (Dn - 1);
        g_x0[i] = (d < NCOND) ? data[i] : x0_noise[i];
    }
    if (gid < Bn * Hn) {
        int bb = gid >> 8, h = gid & (Hn - 1);
        float acc = 0.f;
        #pragma unroll 8
        for (int j = 0; j < Cn; j++)
            acc = fmaf(c[bb * Cn + j], Wc[j * Hn + h], acc);
        g_cc[gid] = acc;
    }

    // ---------------- load RAW data[b] tile + half-norms ------------------
    {
        const float4* dptr = (const float4*)(data + (size_t)b * Nn * Dn);
        for (int i = t; i < Nn * 2; i += TPB) {
            int m = i >> 1;
            sdata[SIDX(m) + (i & 1)] = dptr[i];
        }
        __syncthreads();
        for (int m = t; m < Nn; m += TPB) {
            float4 a = sdata[SIDX(m)];
            float4 bb2 = sdata[SIDX(m) + 1];
            float s = a.x * a.x;
            s = fmaf(a.y, a.y, s);  s = fmaf(a.z, a.z, s);
            s = fmaf(a.w, a.w, s);  s = fmaf(bb2.x, bb2.x, s);
            s = fmaf(bb2.y, bb2.y, s); s = fmaf(bb2.z, bb2.z, s);
            s = fmaf(bb2.w, bb2.w, s);
            shm[HIDX(m)] = 0.5f * s;
        }
    }
    gbar(0);

    const int sbase32 = 65 * lane;       // SIDX(lane*32)
    const int hbase32 = 33 * lane;       // HIDX(lane*32)

    // ---------------- phase 1: mismatch predicate, 4 rows/warp, early exit
    // mismatch(n) <=> exists m: score_m < score_self || (== && m < n)
    #pragma unroll 1
    for (int pass = 0; pass < 2; pass++) {
        float nx[4][8];
        float ss[4];
        int rown[4];
        unsigned int found = 0u;
        #pragma unroll
        for (int j = 0; j < 4; j++) {
            rown[j] = tile * 128 + pass * 64 + wid * 4 + j;
            const float4* xr =
                (const float4*)(g_x0 + ((size_t)b * Nn + rown[j]) * Dn);
            float4 v0 = xr[0], v1 = xr[1];          // broadcast
            nx[j][0] = -v0.x; nx[j][1] = -v0.y; nx[j][2] = -v0.z; nx[j][3] = -v0.w;
            nx[j][4] = -v1.x; nx[j][5] = -v1.y; nx[j][6] = -v1.z; nx[j][7] = -v1.w;
            float4 sa = sdata[SIDX(rown[j])];
            float4 sb = sdata[SIDX(rown[j]) + 1];
            ss[j] = score8(nx[j], sa, sb, shm[HIDX(rown[j])]);
        }
        #pragma unroll 1
        for (int i8 = 0; i8 < 4; i8++) {
            #pragma unroll
            for (int k = 0; k < 8; k++) {
                int i = i8 * 8 + k;
                float4 da = sdata[sbase32 + 2 * i];
                float4 db = sdata[sbase32 + 2 * i + 1];
                float hm = shm[hbase32 + i];
                int m = lane * 32 + i;
                #pragma unroll
                for (int j = 0; j < 4; j++) {
                    float s = score8(nx[j], da, db, hm);
                    unsigned int hit = (unsigned int)((s < ss[j]) |
                                       ((s == ss[j]) & (m < rown[j])));
                    found |= hit << j;
                }
            }
            if (__reduce_or_sync(0xffffffffu, found) == 0xFu) break;
        }
        unsigned int warpFound = __reduce_or_sync(0xffffffffu, found);
        if (lane == 0) {
            int nm = 0, mr[4];
            #pragma unroll
            for (int j = 0; j < 4; j++)
                if ((warpFound >> j) & 1u) mr[nm++] = rown[j];
            if (nm) {
                int s = atomicAdd(&g_cnt[0][b], nm);
                for (int k = 0; k < nm; k++) g_lists[0][b][s + k] = mr[k];
            }
        }
    }
    gbar(1);

    // ---------------- phase 2: iterative renoise (smem tile reuse) --------
    // Unmasked rows invariant => only listed rows renoised + rechecked.
    const int wb = (bid & 7) * 16 + wid;   // warp index within batch: 0..127
    for (int it = 0; it < MAXIT; it++) {
        int total = 0;
        #pragma unroll
        for (int i = 0; i < Bn; i++) total += g_cnt[it][i];
        if (total >= 10) {               // while-loop condition (global mask sum)
            const int cnt = g_cnt[it][b];
            const int* src = g_lists[it & 1][b];
            int*       dst = g_lists[(it + 1) & 1][b];
            const int ng = (cnt + 3) >> 2;          // 4 rows per warp-group
            for (int g = wb; g < ng; g += 128) {
                float nx[4][8];
                float ss[4];
                int rn[4];
                unsigned int valmask = 0u, found = 0u;
                #pragma unroll
                for (int j = 0; j < 4; j++) {
                    int li = g * 4 + j;
                    bool val = li < cnt;
                    valmask |= ((unsigned int)val) << j;
                    found |= ((unsigned int)!val) << j;   // invalid: pre-decided
                    rn[j] = val ? src[li] : 0;
                    int rf = b * Nn + rn[j];
                    // x row = [data dims 0-2, noise_bank[it] dims 3-7]
                    float4 dA = ((const float4*)data)[(size_t)rf * 2];
                    const float4* np =
                        (const float4*)(noise_bank + ((size_t)it * NROWS + rf) * Dn);
                    float4 nA = np[0], nB = np[1];
                    nx[j][0] = -dA.x; nx[j][1] = -dA.y; nx[j][2] = -dA.z;
                    nx[j][3] = -nA.w;
                    nx[j][4] = -nB.x; nx[j][5] = -nB.y; nx[j][6] = -nB.z;
                    nx[j][7] = -nB.w;
                    if (lane == 0 && val) {          // persist renoise for phase 3
                        g_x0[(size_t)rf * Dn + 3] = nA.w;
                        *((float4*)(g_x0 + (size_t)rf * Dn + 4)) = nB;
                    }
                    float4 sa = sdata[SIDX(rn[j])];
                    float4 sb = sdata[SIDX(rn[j]) + 1];
                    ss[j] = score8(nx[j], sa, sb, shm[HIDX(rn[j])]);
                }
                #pragma unroll 1
                for (int i8 = 0; i8 < 4; i8++) {
                    #pragma unroll
                    for (int k = 0; k < 8; k++) {
                        int i = i8 * 8 + k;
                        float4 da = sdata[sbase32 + 2 * i];
                        float4 db = sdata[sbase32 + 2 * i + 1];
                        float hm = shm[hbase32 + i];
                        int m = lane * 32 + i;
                        #pragma unroll
                        for (int j = 0; j < 4; j++) {
                            float s = score8(nx[j], da, db, hm);
                            unsigned int hit = (unsigned int)((s < ss[j]) |
                                               ((s == ss[j]) & (m < rn[j])));
                            found |= hit << j;
                        }
                    }
                    if (__reduce_or_sync(0xffffffffu, found) == 0xFu) break;
                }
                unsigned int warpFound = __reduce_or_sync(0xffffffffu, found);
                if (lane == 0) {
                    unsigned int mis = warpFound & valmask;
                    int nm = 0, mr[4];
                    #pragma unroll
                    for (int j = 0; j < 4; j++)
                        if ((mis >> j) & 1u) mr[nm++] = rn[j];
                    if (nm) {
                        int s = atomicAdd(&g_cnt[it + 1][b], nm);
                        for (int k = 0; k < nm; k++) dst[s + k] = mr[k];
                    }
                }
            }
        }
        gbar(2 + it);
    }

    // ---------------- phase 3: fused model + masked loss ------------------
    {
        for (int i = t; i < Dn * Hn; i += TPB) sW1[i] = W1[i];
        for (int i = t; i < Hn * Dn; i += TPB) sW2[i] = W2[i];
        const float tb = tv[b];
        if (t < Hn)
            sbase[t] = g_cc[b * Hn + t] + tb * Wt[t] + b1[t];
        __syncthreads();

        const int q   = t & 3;            // h-quarter: [q*64, q*64+64)
        const int r   = t >> 2;           // 0..127
        const int row = tile * 128 + r;
        const int base = (b * Nn + row) * Dn;

        float xt[Dn], ut[Dn], vt[Dn];
        #pragma unroll
        for (int d = 0; d < Dn; d++) {
            float dv = data[base + d];
            float xv = g_x0[base + d];
            ut[d] = dv - xv;
            xt[d] = (d < NCOND) ? dv : ((1.0f - tb) * xv + tb * dv);
            vt[d] = 0.f;
        }
        const int h0 = q * (Hn / 4);
        for (int h = h0; h < h0 + Hn / 4; h++) {
            float pre = sbase[h];
            #pragma unroll
            for (int d = 0; d < Dn; d++) pre = fmaf(xt[d], sW1[d * Hn + h], pre);
            float hh = tanh_fast(pre);
            #pragma unroll
            for (int d = 0; d < Dn; d++) vt[d] = fmaf(hh, sW2[h * Dn + d], vt[d]);
        }
        // merge h-quarters (lanes 4r..4r+3)
        #pragma unroll
        for (int off = 2; off >= 1; off >>= 1) {
            #pragma unroll
            for (int d = 0; d < Dn; d++)
                vt[d] += __shfl_down_sync(0xffffffffu, vt[d], off, 4);
        }
        float part = 0.f;
        if (q == 0) {
            #pragma unroll
            for (int d = NCOND; d < Dn; d++) {
                float e = vt[d] - ut[d];
                part = fmaf(e, e, part);
            }
        }
        sred[t] = part;
        __syncthreads();
        // deterministic tree reduction
        for (int s = TPB / 2; s > 0; s >>= 1) {
            if (t < s) sred[t] += sred[t + s];
            __syncthreads();
        }
        if (t == 0) g_partial[bid] = sred[0];
    }
    gbar(6);

    // ---------------- phase 4: per-batch deterministic sum ----------------
    if (bid == 0 && t < Bn) {
        float s = 0.f;
        #pragma unroll
        for (int i = 0; i < 8; i++) s += g_partial[t * 8 + i];
        out[t] = s / (float)(Nn * (Dn - NCOND));
    }
}

// ---------------- launch: ONE graph node ----------------------------------
extern "C" void kernel_launch(void* const* d_in, const int* in_sizes, int n_in,
                              void* d_out, int out_size) {
    const float* data = (const float*)d_in[0];
    const float* c    = (const float*)d_in[1];
    const float* t    = (const float*)d_in[2];
    const float* x0n  = (const float*)d_in[3];
    const float* nb   = (const float*)d_in[4];
    const float* W1   = (const float*)d_in[5];
    const float* Wc   = (const float*)d_in[6];
    const float* Wt   = (const float*)d_in[7];
    const float* b1   = (const float*)d_in[8];
    const float* W2   = (const float*)d_in[9];
    float* out = (float*)d_out;

    k_fused<<<GRID, TPB>>>(data, c, t, x0n, nb, W1, Wc, Wt, b1, W2, out);
}